// round 1
// baseline (speedup 1.0000x reference)
#include <cuda_runtime.h>
#include <math.h>

#define H  1024
#define ML 4096
#define V  128000

// ------------------------- device scratch -------------------------
__device__ float    g_cat[2 * H];          // [e0, h0]
__device__ float    g_alog[ML];            // attention logits
__device__ float    g_aw[ML];              // attention weights (softmax)
__device__ float    g_ctx_part[32][H];     // split-K partials for context
__device__ float    g_cat2[2 * H];         // [e0, ctx]
__device__ float    g_x[H];                // relu(combine)
__device__ float    g_gi[3 * H];
__device__ float    g_gh[3 * H];
__device__ float    g_hnew[H];
__device__ float    g_blog[V];             // vocab logits
__device__ unsigned g_maxbits;             // order-flipped float max
__device__ float    g_psum[512];           // sum-exp partials
__device__ float    g_lse;                 // max + log(sumexp)

// ------------------------- helpers -------------------------
__device__ __forceinline__ float wsum(float v) {
#pragma unroll
    for (int o = 16; o; o >>= 1) v += __shfl_xor_sync(0xffffffffu, v, o);
    return v;
}
__device__ __forceinline__ float wmax(float v) {
#pragma unroll
    for (int o = 16; o; o >>= 1) v = fmaxf(v, __shfl_xor_sync(0xffffffffu, v, o));
    return v;
}
// monotone float <-> uint mapping (for deterministic atomicMax on floats)
__device__ __forceinline__ unsigned fflip(float f) {
    unsigned u = __float_as_uint(f);
    return (u & 0x80000000u) ? ~u : (u | 0x80000000u);
}
__device__ __forceinline__ float funflip(unsigned u) {
    return __uint_as_float((u & 0x80000000u) ? (u ^ 0x80000000u) : ~u);
}

// ------------------------- K0: gather embedding + concat, reset max -------------------------
__global__ void k0_cat(const int* __restrict__ ids, const float* __restrict__ hidden,
                       const float* __restrict__ emb) {
    int j = blockIdx.x * 256 + threadIdx.x;
    if (j == 0) g_maxbits = 0u;
    if (j < 2 * H) {
        int id = ids[0];
        g_cat[j] = (j < H) ? emb[(long)id * H + j] : hidden[j - H];
    }
}

// ------------------------- K1: attention logits = attn_w @ cat + attn_b -------------------------
// one warp per row (2048-wide dot), 8 rows/block, grid 512
__global__ void k1_attn(const float* __restrict__ attn_w, const float* __restrict__ attn_b) {
    __shared__ float4 sv[512];
    int t = threadIdx.x;
    const float4* cat4 = (const float4*)g_cat;
    for (int i = t; i < 512; i += 256) sv[i] = cat4[i];
    __syncthreads();
    int warp = t >> 5, lane = t & 31;
    int row = blockIdx.x * 8 + warp;
    const float4* w4 = (const float4*)(attn_w + (long)row * 2048);
    float acc = 0.f;
#pragma unroll
    for (int i = 0; i < 16; i++) {
        float4 a = w4[lane + i * 32];
        float4 b = sv[lane + i * 32];
        acc += a.x * b.x + a.y * b.y + a.z * b.z + a.w * b.w;
    }
    acc = wsum(acc);
    if (lane == 0) g_alog[row] = acc + attn_b[row];
}

// ------------------------- K2: softmax over ML=4096 (one block, 1024 threads) -------------------------
__global__ void k2_softmax(float* __restrict__ out_aw) {
    __shared__ float red[32];
    __shared__ float smax, ssum;
    int t = threadIdx.x;
    float v[4];
#pragma unroll
    for (int i = 0; i < 4; i++) v[i] = g_alog[t + i * 1024];
    float m = fmaxf(fmaxf(v[0], v[1]), fmaxf(v[2], v[3]));
    m = wmax(m);
    if ((t & 31) == 0) red[t >> 5] = m;
    __syncthreads();
    if (t < 32) { float x = red[t]; x = wmax(x); if (t == 0) smax = x; }
    __syncthreads();
    float M = smax;
    float s = 0.f;
#pragma unroll
    for (int i = 0; i < 4; i++) { v[i] = expf(v[i] - M); s += v[i]; }
    s = wsum(s);
    if ((t & 31) == 0) red[t >> 5] = s;
    __syncthreads();
    if (t < 32) { float x = red[t]; x = wsum(x); if (t == 0) ssum = x; }
    __syncthreads();
    float inv = 1.f / ssum;
#pragma unroll
    for (int i = 0; i < 4; i++) {
        float w = v[i] * inv;
        g_aw[t + i * 1024]  = w;
        out_aw[t + i * 1024] = w;
    }
}

// ------------------------- K3: context split-K partials -------------------------
// grid (4, 32): x covers H in 256-chunks, y covers ML in 128-row chunks
__global__ void k3_ctx(const float* __restrict__ enc) {
    int j = blockIdx.x * 256 + threadIdx.x;
    int c = blockIdx.y;
    int i0 = c * 128;
    float acc = 0.f;
#pragma unroll 4
    for (int i = 0; i < 128; i++) acc += g_aw[i0 + i] * enc[(long)(i0 + i) * H + j];
    g_ctx_part[c][j] = acc;
}

// ------------------------- K4a: reduce partials + build cat2 = [e0, ctx] -------------------------
__global__ void k4a_cat2() {
    int j = blockIdx.x * 256 + threadIdx.x;
    if (j < H) {
        g_cat2[j] = g_cat[j];
    } else if (j < 2 * H) {
        int c = j - H;
        float s = 0.f;
#pragma unroll
        for (int k = 0; k < 32; k++) s += g_ctx_part[k][c];
        g_cat2[j] = s;
    }
}

// ------------------------- K4b: x = relu(comb_w @ cat2 + comb_b) -------------------------
__global__ void k4b_x(const float* __restrict__ comb_w, const float* __restrict__ comb_b) {
    __shared__ float4 sv[512];
    int t = threadIdx.x;
    const float4* c4 = (const float4*)g_cat2;
    for (int i = t; i < 512; i += 256) sv[i] = c4[i];
    __syncthreads();
    int warp = t >> 5, lane = t & 31;
    int row = blockIdx.x * 8 + warp;
    const float4* w4 = (const float4*)(comb_w + (long)row * 2048);
    float acc = 0.f;
#pragma unroll
    for (int i = 0; i < 16; i++) {
        float4 a = w4[lane + i * 32];
        float4 b = sv[lane + i * 32];
        acc += a.x * b.x + a.y * b.y + a.z * b.z + a.w * b.w;
    }
    acc = wsum(acc);
    if (lane == 0) g_x[row] = fmaxf(acc + comb_b[row], 0.f);
}

// ------------------------- K5: gi = w_ih @ x + b_ih ; gh = w_hh @ h0 + b_hh -------------------------
// 6144 warp-rows total, grid 768
__global__ void k5_gates(const float* __restrict__ w_ih, const float* __restrict__ w_hh,
                         const float* __restrict__ b_ih, const float* __restrict__ b_hh,
                         const float* __restrict__ hidden) {
    __shared__ float4 sx[256];
    __shared__ float4 sh[256];
    int t = threadIdx.x;
    sx[t] = ((const float4*)g_x)[t];
    sh[t] = ((const float4*)hidden)[t];
    __syncthreads();
    int warp = t >> 5, lane = t & 31;
    int row = blockIdx.x * 8 + warp;   // 0..6143
    const float*  W;
    const float4* vec;
    float*        out;
    const float*  bias;
    int r;
    if (row < 3072) { W = w_ih; vec = sx; out = g_gi; bias = b_ih; r = row; }
    else            { W = w_hh; vec = sh; out = g_gh; bias = b_hh; r = row - 3072; }
    const float4* w4 = (const float4*)(W + (long)r * H);
    float acc = 0.f;
#pragma unroll
    for (int i = 0; i < 8; i++) {
        float4 a = w4[lane + i * 32];
        float4 b = vec[lane + i * 32];
        acc += a.x * b.x + a.y * b.y + a.z * b.z + a.w * b.w;
    }
    acc = wsum(acc);
    if (lane == 0) out[r] = acc + bias[r];
}

// ------------------------- K6: GRU combine -------------------------
__global__ void k6_gru(const float* __restrict__ hidden, float* __restrict__ out_h) {
    int j = blockIdx.x * 256 + threadIdx.x;  // grid 4
    float r = 1.f / (1.f + expf(-(g_gi[j] + g_gh[j])));
    float z = 1.f / (1.f + expf(-(g_gi[H + j] + g_gh[H + j])));
    float n = tanhf(g_gi[2 * H + j] + r * g_gh[2 * H + j]);
    float h = (1.f - z) * n + z * hidden[j];
    g_hnew[j] = h;
    out_h[j]  = h;
}

// ------------------------- K7: vocab logits + running max (THE big one, 512 MB) -------------------------
// one warp per row, 8 rows/block, grid 16000
__global__ void k7_logits(const float* __restrict__ out_w, const float* __restrict__ out_b) {
    __shared__ float4 sh[256];
    __shared__ float red[8];
    int t = threadIdx.x;
    sh[t] = ((const float4*)g_hnew)[t];
    __syncthreads();
    int warp = t >> 5, lane = t & 31;
    int row = blockIdx.x * 8 + warp;
    const float4* w4 = (const float4*)(out_w + (long)row * H);
    float acc = 0.f;
#pragma unroll
    for (int i = 0; i < 8; i++) {
        float4 a = w4[lane + i * 32];
        float4 b = sh[lane + i * 32];
        acc += a.x * b.x + a.y * b.y + a.z * b.z + a.w * b.w;
    }
    acc = wsum(acc);
    float l = acc + out_b[row];
    if (lane == 0) { g_blog[row] = l; red[warp] = l; }
    __syncthreads();
    if (t == 0) {
        float m = red[0];
#pragma unroll
        for (int i = 1; i < 8; i++) m = fmaxf(m, red[i]);
        atomicMax(&g_maxbits, fflip(m));  // max is commutative -> deterministic
    }
}

// ------------------------- K8: sum-exp partials (fixed slots -> deterministic) -------------------------
__global__ void k8_psum() {
    __shared__ float red[8];
    int t = threadIdx.x;
    float M = funflip(g_maxbits);
    int base = blockIdx.x * 250;  // 512 * 250 = 128000
    float acc = (t < 250) ? expf(g_blog[base + t] - M) : 0.f;
    acc = wsum(acc);
    if ((t & 31) == 0) red[t >> 5] = acc;
    __syncthreads();
    if (t == 0) {
        float s = 0.f;
#pragma unroll
        for (int i = 0; i < 8; i++) s += red[i];
        g_psum[blockIdx.x] = s;
    }
}

// ------------------------- K9: final log-sum-exp -------------------------
__global__ void k9_lse() {
    __shared__ float red[16];
    int t = threadIdx.x;  // 512
    float v = g_psum[t];
    v = wsum(v);
    if ((t & 31) == 0) red[t >> 5] = v;
    __syncthreads();
    if (t == 0) {
        float s = 0.f;
#pragma unroll
        for (int i = 0; i < 16; i++) s += red[i];
        g_lse = funflip(g_maxbits) + logf(s);
    }
}

// ------------------------- K10: write log-softmax -------------------------
__global__ void k10_out(float* __restrict__ out) {
    int v = blockIdx.x * 256 + threadIdx.x;  // grid 500
    out[v] = g_blog[v] - g_lse;
}

// ------------------------- launch -------------------------
extern "C" void kernel_launch(void* const* d_in, const int* in_sizes, int n_in,
                              void* d_out, int out_size) {
    const int*   ids    = (const int*)d_in[0];
    const float* hidden = (const float*)d_in[1];
    const float* enc    = (const float*)d_in[2];
    const float* emb    = (const float*)d_in[3];
    const float* attn_w = (const float*)d_in[4];
    const float* attn_b = (const float*)d_in[5];
    const float* comb_w = (const float*)d_in[6];
    const float* comb_b = (const float*)d_in[7];
    const float* w_ih   = (const float*)d_in[8];
    const float* w_hh   = (const float*)d_in[9];
    const float* b_ih   = (const float*)d_in[10];
    const float* b_hh   = (const float*)d_in[11];
    const float* out_w  = (const float*)d_in[12];
    const float* out_b  = (const float*)d_in[13];
    float* out = (float*)d_out;

    k0_cat<<<8, 256>>>(ids, hidden, emb);
    k1_attn<<<512, 256>>>(attn_w, attn_b);
    k2_softmax<<<1, 1024>>>(out + V + H);
    k3_ctx<<<dim3(4, 32), 256>>>(enc);
    k4a_cat2<<<8, 256>>>();
    k4b_x<<<128, 256>>>(comb_w, comb_b);
    k5_gates<<<768, 256>>>(w_ih, w_hh, b_ih, b_hh, hidden);
    k6_gru<<<4, 256>>>(hidden, out + V);
    k7_logits<<<16000, 256>>>(out_w, out_b);
    k8_psum<<<512, 256>>>();
    k9_lse<<<1, 512>>>();
    k10_out<<<500, 256>>>(out);
}

// round 2
// speedup vs baseline: 1.0815x; 1.0815x over previous
#include <cuda_runtime.h>
#include <math.h>

#define H  1024
#define ML 4096
#define V  128000

// ------------------------- device scratch -------------------------
__device__ float    g_alog[ML];            // attention logits
__device__ float    g_aw[ML];              // attention weights (softmax)
__device__ float    g_ctx_part[256][H];    // split-K partials for context
__device__ float    g_cat2[2 * H];         // [e0, ctx]
__device__ float    g_x[H];                // relu(combine)
__device__ float    g_gi[3 * H];
__device__ float    g_gh[3 * H];
__device__ float    g_hnew[H];
__device__ float    g_blog[V];             // vocab logits
__device__ unsigned g_maxbits;             // order-flipped float max
__device__ float    g_psum[512];           // sum-exp partials
__device__ float    g_lse;                 // max + log(sumexp)

// ------------------------- helpers -------------------------
__device__ __forceinline__ float wsum(float v) {
#pragma unroll
    for (int o = 16; o; o >>= 1) v += __shfl_xor_sync(0xffffffffu, v, o);
    return v;
}
__device__ __forceinline__ float wmax(float v) {
#pragma unroll
    for (int o = 16; o; o >>= 1) v = fmaxf(v, __shfl_xor_sync(0xffffffffu, v, o));
    return v;
}
// monotone float <-> uint mapping (deterministic atomicMax on floats)
__device__ __forceinline__ unsigned fflip(float f) {
    unsigned u = __float_as_uint(f);
    return (u & 0x80000000u) ? ~u : (u | 0x80000000u);
}
__device__ __forceinline__ float funflip(unsigned u) {
    return __uint_as_float((u & 0x80000000u) ? (u ^ 0x80000000u) : ~u);
}
__device__ __forceinline__ float dot4(float4 a, float4 b) {
    return a.x * b.x + a.y * b.y + a.z * b.z + a.w * b.w;
}

// ------------------------- K1: attention logits = attn_w @ [e0,h0] + attn_b -------------------------
// one warp per row (2048-wide dot), 8 rows/block, grid 512
__global__ void k1_attn(const int* __restrict__ ids, const float* __restrict__ hidden,
                        const float* __restrict__ emb,
                        const float* __restrict__ attn_w, const float* __restrict__ attn_b) {
    __shared__ float4 sv[512];
    int t = threadIdx.x;
    int id = ids[0];
    const float4* e4 = (const float4*)(emb + (long)id * H);
    const float4* h4 = (const float4*)hidden;
    for (int i = t; i < 512; i += 256) sv[i] = (i < 256) ? e4[i] : h4[i - 256];
    __syncthreads();
    int warp = t >> 5, lane = t & 31;
    int row = blockIdx.x * 8 + warp;
    const float4* w4 = (const float4*)(attn_w + (long)row * 2048);
    float acc = 0.f;
#pragma unroll
    for (int i = 0; i < 16; i++)
        acc += dot4(__ldcs(&w4[lane + i * 32]), sv[lane + i * 32]);
    acc = wsum(acc);
    if (lane == 0) g_alog[row] = acc + attn_b[row];
}

// ------------------------- K2: softmax over ML=4096 (one block, 1024 threads) -------------------------
__global__ void k2_softmax(float* __restrict__ out_aw) {
    __shared__ float red[32];
    __shared__ float smax, ssum;
    int t = threadIdx.x;
    if (t == 0) g_maxbits = 0u;   // reset running max for this call (graph-replay safe)
    float v[4];
#pragma unroll
    for (int i = 0; i < 4; i++) v[i] = g_alog[t + i * 1024];
    float m = fmaxf(fmaxf(v[0], v[1]), fmaxf(v[2], v[3]));
    m = wmax(m);
    if ((t & 31) == 0) red[t >> 5] = m;
    __syncthreads();
    if (t < 32) { float x = red[t]; x = wmax(x); if (t == 0) smax = x; }
    __syncthreads();
    float M = smax;
    float s = 0.f;
#pragma unroll
    for (int i = 0; i < 4; i++) { v[i] = expf(v[i] - M); s += v[i]; }
    s = wsum(s);
    if ((t & 31) == 0) red[t >> 5] = s;
    __syncthreads();
    if (t < 32) { float x = red[t]; x = wsum(x); if (t == 0) ssum = x; }
    __syncthreads();
    float inv = 1.f / ssum;
#pragma unroll
    for (int i = 0; i < 4; i++) {
        float w = v[i] * inv;
        g_aw[t + i * 1024]   = w;
        out_aw[t + i * 1024] = w;
    }
}

// ------------------------- K3: context split-K partials -------------------------
// 256 chunks of 16 rows; each block covers all H=1024 cols via float4 (256 thr x 4)
__global__ void k3_ctx(const float* __restrict__ enc) {
    int t = threadIdx.x;          // 0..255 -> float4 column group
    int c = blockIdx.x;           // 0..255 chunk
    int i0 = c * 16;
    const float4* e4 = (const float4*)enc;
    float4 acc = make_float4(0.f, 0.f, 0.f, 0.f);
#pragma unroll
    for (int i = 0; i < 16; i++) {
        float w = g_aw[i0 + i];
        float4 v = __ldcs(&e4[(long)(i0 + i) * 256 + t]);
        acc.x += w * v.x; acc.y += w * v.y; acc.z += w * v.z; acc.w += w * v.w;
    }
    ((float4*)g_ctx_part)[c * 256 + t] = acc;
}

// ------------------------- K4a: reduce partials + build cat2 = [e0, ctx] -------------------------
__global__ void k4a_cat2(const int* __restrict__ ids, const float* __restrict__ emb) {
    int j = blockIdx.x * 256 + threadIdx.x;   // grid 8 -> 2048
    if (j < H) {
        g_cat2[j] = emb[(long)ids[0] * H + j];
    } else {
        int c = j - H;
        float s = 0.f;
#pragma unroll 8
        for (int k = 0; k < 256; k++) s += g_ctx_part[k][c];
        g_cat2[j] = s;
    }
}

// ------------------------- K4b: x = relu(comb_w @ cat2 + comb_b) -------------------------
__global__ void k4b_x(const float* __restrict__ comb_w, const float* __restrict__ comb_b) {
    __shared__ float4 sv[512];
    int t = threadIdx.x;
    const float4* c4 = (const float4*)g_cat2;
    for (int i = t; i < 512; i += 256) sv[i] = c4[i];
    __syncthreads();
    int warp = t >> 5, lane = t & 31;
    int row = blockIdx.x * 8 + warp;
    const float4* w4 = (const float4*)(comb_w + (long)row * 2048);
    float acc = 0.f;
#pragma unroll
    for (int i = 0; i < 16; i++)
        acc += dot4(__ldcs(&w4[lane + i * 32]), sv[lane + i * 32]);
    acc = wsum(acc);
    if (lane == 0) g_x[row] = fmaxf(acc + comb_b[row], 0.f);
}

// ------------------------- K5: gi = w_ih @ x + b_ih ; gh = w_hh @ h0 + b_hh -------------------------
__global__ void k5_gates(const float* __restrict__ w_ih, const float* __restrict__ w_hh,
                         const float* __restrict__ b_ih, const float* __restrict__ b_hh,
                         const float* __restrict__ hidden) {
    __shared__ float4 sx[256];
    __shared__ float4 sh[256];
    int t = threadIdx.x;
    sx[t] = ((const float4*)g_x)[t];
    sh[t] = ((const float4*)hidden)[t];
    __syncthreads();
    int warp = t >> 5, lane = t & 31;
    int row = blockIdx.x * 8 + warp;   // 0..6143
    const float*  W;
    const float4* vec;
    float*        out;
    const float*  bias;
    int r;
    if (row < 3072) { W = w_ih; vec = sx; out = g_gi; bias = b_ih; r = row; }
    else            { W = w_hh; vec = sh; out = g_gh; bias = b_hh; r = row - 3072; }
    const float4* w4 = (const float4*)(W + (long)r * H);
    float acc = 0.f;
#pragma unroll
    for (int i = 0; i < 8; i++)
        acc += dot4(__ldcs(&w4[lane + i * 32]), vec[lane + i * 32]);
    acc = wsum(acc);
    if (lane == 0) out[r] = acc + bias[r];
}

// ------------------------- K6: GRU combine -------------------------
__global__ void k6_gru(const float* __restrict__ hidden, float* __restrict__ out_h) {
    int j = blockIdx.x * 256 + threadIdx.x;  // grid 4
    float r = 1.f / (1.f + expf(-(g_gi[j] + g_gh[j])));
    float z = 1.f / (1.f + expf(-(g_gi[H + j] + g_gh[H + j])));
    float n = tanhf(g_gi[2 * H + j] + r * g_gh[2 * H + j]);
    float h = (1.f - z) * n + z * hidden[j];
    g_hnew[j] = h;
    out_h[j]  = h;
}

// ------------------------- K7: vocab logits + running max (512 MB stream) -------------------------
// one warp per row, 8 rows/block, grid 16000
__global__ void k7_logits(const float* __restrict__ out_w, const float* __restrict__ out_b) {
    __shared__ float4 sh[256];
    __shared__ float red[8];
    int t = threadIdx.x;
    sh[t] = ((const float4*)g_hnew)[t];
    __syncthreads();
    int warp = t >> 5, lane = t & 31;
    int row = blockIdx.x * 8 + warp;
    const float4* w4 = (const float4*)(out_w + (long)row * H);
    float acc = 0.f;
#pragma unroll
    for (int i = 0; i < 8; i++)
        acc += dot4(__ldcs(&w4[lane + i * 32]), sh[lane + i * 32]);
    acc = wsum(acc);
    float l = acc + out_b[row];
    if (lane == 0) { g_blog[row] = l; red[warp] = l; }
    __syncthreads();
    if (t == 0) {
        float m = red[0];
#pragma unroll
        for (int i = 1; i < 8; i++) m = fmaxf(m, red[i]);
        atomicMax(&g_maxbits, fflip(m));  // max commutative -> deterministic
    }
}

// ------------------------- K8: sum-exp partials (fixed slots -> deterministic) -------------------------
__global__ void k8_psum() {
    __shared__ float red[8];
    int t = threadIdx.x;
    float M = funflip(g_maxbits);
    int base = blockIdx.x * 250;  // 512 * 250 = 128000
    float acc = (t < 250) ? expf(g_blog[base + t] - M) : 0.f;
    acc = wsum(acc);
    if ((t & 31) == 0) red[t >> 5] = acc;
    __syncthreads();
    if (t == 0) {
        float s = 0.f;
#pragma unroll
        for (int i = 0; i < 8; i++) s += red[i];
        g_psum[blockIdx.x] = s;
    }
}

// ------------------------- K9: final log-sum-exp -------------------------
__global__ void k9_lse() {
    __shared__ float red[16];
    int t = threadIdx.x;  // 512
    float v = g_psum[t];
    v = wsum(v);
    if ((t & 31) == 0) red[t >> 5] = v;
    __syncthreads();
    if (t == 0) {
        float s = 0.f;
#pragma unroll
        for (int i = 0; i < 16; i++) s += red[i];
        g_lse = funflip(g_maxbits) + logf(s);
    }
}

// ------------------------- K10: write log-softmax -------------------------
__global__ void k10_out(float* __restrict__ out) {
    int v = blockIdx.x * 256 + threadIdx.x;  // grid 500
    out[v] = g_blog[v] - g_lse;
}

// ------------------------- launch -------------------------
extern "C" void kernel_launch(void* const* d_in, const int* in_sizes, int n_in,
                              void* d_out, int out_size) {
    const int*   ids    = (const int*)d_in[0];
    const float* hidden = (const float*)d_in[1];
    const float* enc    = (const float*)d_in[2];
    const float* emb    = (const float*)d_in[3];
    const float* attn_w = (const float*)d_in[4];
    const float* attn_b = (const float*)d_in[5];
    const float* comb_w = (const float*)d_in[6];
    const float* comb_b = (const float*)d_in[7];
    const float* w_ih   = (const float*)d_in[8];
    const float* w_hh   = (const float*)d_in[9];
    const float* b_ih   = (const float*)d_in[10];
    const float* b_hh   = (const float*)d_in[11];
    const float* out_w  = (const float*)d_in[12];
    const float* out_b  = (const float*)d_in[13];
    float* out = (float*)d_out;

    k1_attn<<<512, 256>>>(ids, hidden, emb, attn_w, attn_b);
    k2_softmax<<<1, 1024>>>(out + V + H);
    k3_ctx<<<256, 256>>>(enc);
    k4a_cat2<<<8, 256>>>(ids, emb);
    k4b_x<<<128, 256>>>(comb_w, comb_b);
    k5_gates<<<768, 256>>>(w_ih, w_hh, b_ih, b_hh, hidden);
    k6_gru<<<4, 256>>>(hidden, out + V);
    k7_logits<<<16000, 256>>>(out_w, out_b);
    k8_psum<<<512, 256>>>();
    k9_lse<<<1, 512>>>();
    k10_out<<<500, 256>>>(out);
}

// round 3
// speedup vs baseline: 1.1412x; 1.0552x over previous
#include <cuda_runtime.h>
#include <math.h>

#define H  1024
#define ML 4096
#define V  128000

// ------------------------- device scratch -------------------------
__device__ float    g_alog[ML];            // attention logits
__device__ float    g_aw[ML];              // attention weights (softmax)
__device__ float    g_ctx_part[256][H];    // split-K partials for context
__device__ float    g_ctx_part2[32][H];    // stage-2 partials
__device__ float    g_cat2[2 * H];         // [e0, ctx]
__device__ float    g_x[H];                // relu(combine)
__device__ float    g_gi[3 * H];
__device__ float    g_gh[3 * H];
__device__ float    g_hnew[H];
__device__ float    g_blog[V];             // vocab logits
__device__ unsigned g_maxbits;             // order-flipped float max
__device__ float    g_psum[512];           // sum-exp partials
__device__ float    g_lse;                 // max + log(sumexp)

// ------------------------- helpers -------------------------
__device__ __forceinline__ float wsum(float v) {
#pragma unroll
    for (int o = 16; o; o >>= 1) v += __shfl_xor_sync(0xffffffffu, v, o);
    return v;
}
__device__ __forceinline__ float wmax(float v) {
#pragma unroll
    for (int o = 16; o; o >>= 1) v = fmaxf(v, __shfl_xor_sync(0xffffffffu, v, o));
    return v;
}
// monotone float <-> uint mapping (deterministic atomicMax on floats)
__device__ __forceinline__ unsigned fflip(float f) {
    unsigned u = __float_as_uint(f);
    return (u & 0x80000000u) ? ~u : (u | 0x80000000u);
}
__device__ __forceinline__ float funflip(unsigned u) {
    return __uint_as_float((u & 0x80000000u) ? (u ^ 0x80000000u) : ~u);
}
__device__ __forceinline__ float dot4(float4 a, float4 b) {
    return a.x * b.x + a.y * b.y + a.z * b.z + a.w * b.w;
}

// ------------------------- K1: attention logits = attn_w @ [e0,h0] + attn_b -------------------------
__global__ void k1_attn(const int* __restrict__ ids, const float* __restrict__ hidden,
                        const float* __restrict__ emb,
                        const float* __restrict__ attn_w, const float* __restrict__ attn_b) {
    __shared__ float4 sv[512];
    int t = threadIdx.x;
    int id = ids[0];
    const float4* e4 = (const float4*)(emb + (long)id * H);
    const float4* h4 = (const float4*)hidden;
    for (int i = t; i < 512; i += 256) sv[i] = (i < 256) ? e4[i] : h4[i - 256];
    __syncthreads();
    int warp = t >> 5, lane = t & 31;
    int row = blockIdx.x * 8 + warp;
    const float4* w4 = (const float4*)(attn_w + (long)row * 2048);
    float acc = 0.f;
#pragma unroll
    for (int i = 0; i < 16; i++)
        acc += dot4(__ldcs(&w4[lane + i * 32]), sv[lane + i * 32]);
    acc = wsum(acc);
    if (lane == 0) g_alog[row] = acc + attn_b[row];
}

// ------------------------- K2: softmax over ML=4096 -------------------------
__global__ void k2_softmax(float* __restrict__ out_aw) {
    __shared__ float red[32];
    __shared__ float smax, ssum;
    int t = threadIdx.x;
    if (t == 0) g_maxbits = 0u;   // reset running max (graph-replay safe)
    float v[4];
#pragma unroll
    for (int i = 0; i < 4; i++) v[i] = g_alog[t + i * 1024];
    float m = fmaxf(fmaxf(v[0], v[1]), fmaxf(v[2], v[3]));
    m = wmax(m);
    if ((t & 31) == 0) red[t >> 5] = m;
    __syncthreads();
    if (t < 32) { float x = red[t]; x = wmax(x); if (t == 0) smax = x; }
    __syncthreads();
    float M = smax;
    float s = 0.f;
#pragma unroll
    for (int i = 0; i < 4; i++) { v[i] = expf(v[i] - M); s += v[i]; }
    s = wsum(s);
    if ((t & 31) == 0) red[t >> 5] = s;
    __syncthreads();
    if (t < 32) { float x = red[t]; x = wsum(x); if (t == 0) ssum = x; }
    __syncthreads();
    float inv = 1.f / ssum;
#pragma unroll
    for (int i = 0; i < 4; i++) {
        float w = v[i] * inv;
        g_aw[t + i * 1024]   = w;
        out_aw[t + i * 1024] = w;
    }
}

// ------------------------- K3: context split-K partials -------------------------
// 256 chunks of 16 rows; each block covers all H=1024 cols via float4
__global__ void k3_ctx(const float* __restrict__ enc) {
    int t = threadIdx.x;
    int c = blockIdx.x;           // 0..255
    int i0 = c * 16;
    const float4* e4 = (const float4*)enc;
    float4 acc = make_float4(0.f, 0.f, 0.f, 0.f);
#pragma unroll
    for (int i = 0; i < 16; i++) {
        float w = g_aw[i0 + i];
        float4 v = __ldcs(&e4[(long)(i0 + i) * 256 + t]);
        acc.x += w * v.x; acc.y += w * v.y; acc.z += w * v.z; acc.w += w * v.w;
    }
    ((float4*)g_ctx_part)[c * 256 + t] = acc;
}

// ------------------------- K4a_red1: reduce 256 partial chunks -> 32 -------------------------
// grid 32, 256 threads: block b sums chunks [8b, 8b+8) over all 256 float4 cols
__global__ void k4a_red1() {
    int t = threadIdx.x;
    int b = blockIdx.x;
    const float4* p4 = (const float4*)g_ctx_part;
    float4 acc = make_float4(0.f, 0.f, 0.f, 0.f);
#pragma unroll
    for (int k = 0; k < 8; k++) {
        float4 v = p4[(long)(b * 8 + k) * 256 + t];
        acc.x += v.x; acc.y += v.y; acc.z += v.z; acc.w += v.w;
    }
    ((float4*)g_ctx_part2)[b * 256 + t] = acc;
}

// ------------------------- K4a: final reduce + build cat2 = [e0, ctx] -------------------------
__global__ void k4a_cat2(const int* __restrict__ ids, const float* __restrict__ emb) {
    int j = blockIdx.x * 256 + threadIdx.x;   // grid 8 -> 2048
    if (j < H) {
        g_cat2[j] = emb[(long)ids[0] * H + j];
    } else {
        int c = j - H;
        float s = 0.f;
#pragma unroll
        for (int k = 0; k < 32; k++) s += g_ctx_part2[k][c];
        g_cat2[j] = s;
    }
}

// ------------------------- K4b: x = relu(comb_w @ cat2 + comb_b) -------------------------
__global__ void k4b_x(const float* __restrict__ comb_w, const float* __restrict__ comb_b) {
    __shared__ float4 sv[512];
    int t = threadIdx.x;
    const float4* c4 = (const float4*)g_cat2;
    for (int i = t; i < 512; i += 256) sv[i] = c4[i];
    __syncthreads();
    int warp = t >> 5, lane = t & 31;
    int row = blockIdx.x * 8 + warp;
    const float4* w4 = (const float4*)(comb_w + (long)row * 2048);
    float acc = 0.f;
#pragma unroll
    for (int i = 0; i < 16; i++)
        acc += dot4(__ldcs(&w4[lane + i * 32]), sv[lane + i * 32]);
    acc = wsum(acc);
    if (lane == 0) g_x[row] = fmaxf(acc + comb_b[row], 0.f);
}

// ------------------------- K5: GRU gate matvecs -------------------------
__global__ void k5_gates(const float* __restrict__ w_ih, const float* __restrict__ w_hh,
                         const float* __restrict__ b_ih, const float* __restrict__ b_hh,
                         const float* __restrict__ hidden) {
    __shared__ float4 sx[256];
    __shared__ float4 sh[256];
    int t = threadIdx.x;
    sx[t] = ((const float4*)g_x)[t];
    sh[t] = ((const float4*)hidden)[t];
    __syncthreads();
    int warp = t >> 5, lane = t & 31;
    int row = blockIdx.x * 8 + warp;   // 0..6143
    const float*  W;
    const float4* vec;
    float*        out;
    const float*  bias;
    int r;
    if (row < 3072) { W = w_ih; vec = sx; out = g_gi; bias = b_ih; r = row; }
    else            { W = w_hh; vec = sh; out = g_gh; bias = b_hh; r = row - 3072; }
    const float4* w4 = (const float4*)(W + (long)r * H);
    float acc = 0.f;
#pragma unroll
    for (int i = 0; i < 8; i++)
        acc += dot4(__ldcs(&w4[lane + i * 32]), vec[lane + i * 32]);
    acc = wsum(acc);
    if (lane == 0) out[r] = acc + bias[r];
}

// ------------------------- K6: GRU combine -------------------------
__global__ void k6_gru(const float* __restrict__ hidden, float* __restrict__ out_h) {
    int j = blockIdx.x * 256 + threadIdx.x;  // grid 4
    float r = 1.f / (1.f + expf(-(g_gi[j] + g_gh[j])));
    float z = 1.f / (1.f + expf(-(g_gi[H + j] + g_gh[H + j])));
    float n = tanhf(g_gi[2 * H + j] + r * g_gh[2 * H + j]);
    float h = (1.f - z) * n + z * hidden[j];
    g_hnew[j] = h;
    out_h[j]  = h;
}

// ------------------------- K7: vocab logits + running max (512 MB stream) -------------------------
__global__ void k7_logits(const float* __restrict__ out_w, const float* __restrict__ out_b) {
    __shared__ float4 sh[256];
    __shared__ float red[8];
    int t = threadIdx.x;
    sh[t] = ((const float4*)g_hnew)[t];
    __syncthreads();
    int warp = t >> 5, lane = t & 31;
    int row = blockIdx.x * 8 + warp;
    const float4* w4 = (const float4*)(out_w + (long)row * H);
    float acc = 0.f;
#pragma unroll
    for (int i = 0; i < 8; i++)
        acc += dot4(__ldcs(&w4[lane + i * 32]), sh[lane + i * 32]);
    acc = wsum(acc);
    float l = acc + out_b[row];
    if (lane == 0) { g_blog[row] = l; red[warp] = l; }
    __syncthreads();
    if (t == 0) {
        float m = red[0];
#pragma unroll
        for (int i = 1; i < 8; i++) m = fmaxf(m, red[i]);
        atomicMax(&g_maxbits, fflip(m));  // max commutative -> deterministic
    }
}

// ------------------------- K8: sum-exp partials (fixed slots -> deterministic) -------------------------
__global__ void k8_psum() {
    __shared__ float red[8];
    int t = threadIdx.x;
    float M = funflip(g_maxbits);
    int base = blockIdx.x * 250;  // 512 * 250 = 128000
    float acc = (t < 250) ? expf(g_blog[base + t] - M) : 0.f;
    acc = wsum(acc);
    if ((t & 31) == 0) red[t >> 5] = acc;
    __syncthreads();
    if (t == 0) {
        float s = 0.f;
#pragma unroll
        for (int i = 0; i < 8; i++) s += red[i];
        g_psum[blockIdx.x] = s;
    }
}

// ------------------------- K9: final log-sum-exp -------------------------
__global__ void k9_lse() {
    __shared__ float red[16];
    int t = threadIdx.x;  // 512
    float v = g_psum[t];
    v = wsum(v);
    if ((t & 31) == 0) red[t >> 5] = v;
    __syncthreads();
    if (t == 0) {
        float s = 0.f;
#pragma unroll
        for (int i = 0; i < 16; i++) s += red[i];
        g_lse = funflip(g_maxbits) + logf(s);
    }
}

// ------------------------- K10: write log-softmax -------------------------
__global__ void k10_out(float* __restrict__ out) {
    int v = blockIdx.x * 256 + threadIdx.x;  // grid 500
    out[v] = g_blog[v] - g_lse;
}

// ------------------------- launch -------------------------
extern "C" void kernel_launch(void* const* d_in, const int* in_sizes, int n_in,
                              void* d_out, int out_size) {
    const int*   ids    = (const int*)d_in[0];
    const float* hidden = (const float*)d_in[1];
    const float* enc    = (const float*)d_in[2];
    const float* emb    = (const float*)d_in[3];
    const float* attn_w = (const float*)d_in[4];
    const float* attn_b = (const float*)d_in[5];
    const float* comb_w = (const float*)d_in[6];
    const float* comb_b = (const float*)d_in[7];
    const float* w_ih   = (const float*)d_in[8];
    const float* w_hh   = (const float*)d_in[9];
    const float* b_ih   = (const float*)d_in[10];
    const float* b_hh   = (const float*)d_in[11];
    const float* out_w  = (const float*)d_in[12];
    const float* out_b  = (const float*)d_in[13];
    float* out = (float*)d_out;

    k1_attn<<<512, 256>>>(ids, hidden, emb, attn_w, attn_b);
    k2_softmax<<<1, 1024>>>(out + V + H);
    k3_ctx<<<256, 256>>>(enc);
    k4a_red1<<<32, 256>>>();
    k4a_cat2<<<8, 256>>>(ids, emb);
    k4b_x<<<128, 256>>>(comb_w, comb_b);
    k5_gates<<<768, 256>>>(w_ih, w_hh, b_ih, b_hh, hidden);
    k6_gru<<<4, 256>>>(hidden, out + V);
    k7_logits<<<16000, 256>>>(out_w, out_b);
    k8_psum<<<512, 256>>>();
    k9_lse<<<1, 512>>>();
    k10_out<<<500, 256>>>(out);
}

// round 4
// speedup vs baseline: 1.1457x; 1.0040x over previous
#include <cuda_runtime.h>
#include <math.h>

#define H  1024
#define ML 4096
#define V  128000

// ------------------------- device scratch -------------------------
__device__ float    g_alog[ML];            // attention logits
__device__ float    g_aw[ML];              // attention weights (softmax)
__device__ float    g_ctx_part[32][H];     // split-K partials for context (32 chunks)
__device__ float    g_cat2[2 * H];         // [e0, ctx]
__device__ float    g_x[H];                // relu(combine)
__device__ float    g_gi[3 * H];
__device__ float    g_gh[3 * H];
__device__ float    g_hnew[H];
__device__ float    g_blog[V];             // vocab logits
__device__ unsigned g_maxbits;             // order-flipped float max
__device__ float    g_psum[512];           // sum-exp partials
__device__ float    g_lse;                 // max + log(sumexp)

// ------------------------- helpers -------------------------
__device__ __forceinline__ float wsum(float v) {
#pragma unroll
    for (int o = 16; o; o >>= 1) v += __shfl_xor_sync(0xffffffffu, v, o);
    return v;
}
__device__ __forceinline__ float wmax(float v) {
#pragma unroll
    for (int o = 16; o; o >>= 1) v = fmaxf(v, __shfl_xor_sync(0xffffffffu, v, o));
    return v;
}
// monotone float <-> uint mapping (deterministic atomicMax on floats)
__device__ __forceinline__ unsigned fflip(float f) {
    unsigned u = __float_as_uint(f);
    return (u & 0x80000000u) ? ~u : (u | 0x80000000u);
}
__device__ __forceinline__ float funflip(unsigned u) {
    return __uint_as_float((u & 0x80000000u) ? (u ^ 0x80000000u) : ~u);
}
__device__ __forceinline__ float dot4(float4 a, float4 b) {
    return a.x * b.x + a.y * b.y + a.z * b.z + a.w * b.w;
}
__device__ __forceinline__ void add4(float4& a, float4 b) {
    a.x += b.x; a.y += b.y; a.z += b.z; a.w += b.w;
}

// ------------------------- K1: attention logits = attn_w @ [e0,h0] + attn_b -------------------------
__global__ void k1_attn(const int* __restrict__ ids, const float* __restrict__ hidden,
                        const float* __restrict__ emb,
                        const float* __restrict__ attn_w, const float* __restrict__ attn_b) {
    __shared__ float4 sv[512];
    int t = threadIdx.x;
    int id = ids[0];
    const float4* e4 = (const float4*)(emb + (long)id * H);
    const float4* h4 = (const float4*)hidden;
    for (int i = t; i < 512; i += 256) sv[i] = (i < 256) ? e4[i] : h4[i - 256];
    __syncthreads();
    int warp = t >> 5, lane = t & 31;
    int row = blockIdx.x * 8 + warp;
    const float4* w4 = (const float4*)(attn_w + (long)row * 2048);
    float acc = 0.f;
#pragma unroll
    for (int i = 0; i < 16; i++)
        acc += dot4(__ldcs(&w4[lane + i * 32]), sv[lane + i * 32]);
    acc = wsum(acc);
    if (lane == 0) g_alog[row] = acc + attn_b[row];
}

// ------------------------- K2: softmax over ML=4096 -------------------------
__global__ void k2_softmax(float* __restrict__ out_aw) {
    __shared__ float red[32];
    __shared__ float smax, ssum;
    int t = threadIdx.x;
    if (t == 0) g_maxbits = 0u;   // reset running max (graph-replay safe)
    float v[4];
#pragma unroll
    for (int i = 0; i < 4; i++) v[i] = g_alog[t + i * 1024];
    float m = fmaxf(fmaxf(v[0], v[1]), fmaxf(v[2], v[3]));
    m = wmax(m);
    if ((t & 31) == 0) red[t >> 5] = m;
    __syncthreads();
    if (t < 32) { float x = red[t]; x = wmax(x); if (t == 0) smax = x; }
    __syncthreads();
    float M = smax;
    float s = 0.f;
#pragma unroll
    for (int i = 0; i < 4; i++) { v[i] = expf(v[i] - M); s += v[i]; }
    s = wsum(s);
    if ((t & 31) == 0) red[t >> 5] = s;
    __syncthreads();
    if (t < 32) { float x = red[t]; x = wsum(x); if (t == 0) ssum = x; }
    __syncthreads();
    float inv = 1.f / ssum;
#pragma unroll
    for (int i = 0; i < 4; i++) {
        float w = v[i] * inv;
        g_aw[t + i * 1024]   = w;
        out_aw[t + i * 1024] = w;
    }
}

// ------------------------- K3: context split-K with in-block reduction -------------------------
// grid 256 = 32 chunks x 8 col-groups; block reduces its 128 rows internally.
// Each thread: 16 consecutive rows for one float4 col; smem reduce over 8 phases.
__global__ void k3_ctx(const float* __restrict__ enc) {
    __shared__ float4 sp[8][32];
    int t = threadIdx.x;
    int chunk = blockIdx.x >> 3;       // 0..31
    int g     = blockIdx.x & 7;        // col group 0..7
    int c     = t & 31;                // f4 col within group
    int phase = t >> 5;                // 0..7
    int col   = g * 32 + c;            // f4 col 0..255
    const float4* e4 = (const float4*)enc;
    int r0 = chunk * 128 + phase * 16;
    float4 acc = make_float4(0.f, 0.f, 0.f, 0.f);
#pragma unroll
    for (int k = 0; k < 16; k++) {
        float w = g_aw[r0 + k];
        float4 v = __ldcs(&e4[(long)(r0 + k) * 256 + col]);
        acc.x += w * v.x; acc.y += w * v.y; acc.z += w * v.z; acc.w += w * v.w;
    }
    sp[phase][c] = acc;
    __syncthreads();
    if (phase == 0) {
        float4 s = acc;                // == sp[0][c]
#pragma unroll
        for (int p = 1; p < 8; p++) add4(s, sp[p][c]);
        ((float4*)g_ctx_part)[chunk * 256 + col] = s;
    }
}

// ------------------------- K4a: coalesced final reduce + build cat2 = [e0, ctx] -------------------------
// grid 9: blocks 0-7 reduce 32 chunks for 32 f4-cols each; block 8 copies e0
__global__ void k4a_cat2(const int* __restrict__ ids, const float* __restrict__ emb) {
    int t = threadIdx.x;
    if (blockIdx.x == 8) {
        ((float4*)g_cat2)[t] = ((const float4*)(emb + (long)ids[0] * H))[t];
        return;
    }
    __shared__ float4 sp[8][32];
    int c = t & 31, phase = t >> 5;
    int col = blockIdx.x * 32 + c;     // f4 col 0..255
    const float4* p4 = (const float4*)g_ctx_part;
    float4 acc = make_float4(0.f, 0.f, 0.f, 0.f);
#pragma unroll
    for (int k = 0; k < 4; k++)
        add4(acc, p4[(long)(phase * 4 + k) * 256 + col]);
    sp[phase][c] = acc;
    __syncthreads();
    if (phase == 0) {
        float4 s = acc;
#pragma unroll
        for (int p = 1; p < 8; p++) add4(s, sp[p][c]);
        ((float4*)(g_cat2 + H))[col] = s;
    }
}

// ------------------------- K4b: x = relu(comb_w @ cat2 + comb_b) -------------------------
__global__ void k4b_x(const float* __restrict__ comb_w, const float* __restrict__ comb_b) {
    __shared__ float4 sv[512];
    int t = threadIdx.x;
    const float4* c4 = (const float4*)g_cat2;
    for (int i = t; i < 512; i += 256) sv[i] = c4[i];
    __syncthreads();
    int warp = t >> 5, lane = t & 31;
    int row = blockIdx.x * 8 + warp;
    const float4* w4 = (const float4*)(comb_w + (long)row * 2048);
    float acc = 0.f;
#pragma unroll
    for (int i = 0; i < 16; i++)
        acc += dot4(__ldcs(&w4[lane + i * 32]), sv[lane + i * 32]);
    acc = wsum(acc);
    if (lane == 0) g_x[row] = fmaxf(acc + comb_b[row], 0.f);
}

// ------------------------- K5: GRU gate matvecs, 2 rows/warp -------------------------
// grid 384: 8 warps x 2 rows = 16 rows/block -> 6144 rows
__global__ void k5_gates(const float* __restrict__ w_ih, const float* __restrict__ w_hh,
                         const float* __restrict__ b_ih, const float* __restrict__ b_hh,
                         const float* __restrict__ hidden) {
    __shared__ float4 sx[256];
    __shared__ float4 sh[256];
    int t = threadIdx.x;
    sx[t] = ((const float4*)g_x)[t];
    sh[t] = ((const float4*)hidden)[t];
    __syncthreads();
    int warp = t >> 5, lane = t & 31;
    int row = blockIdx.x * 16 + warp * 2;   // 0..6143, pair within same half
    const float*  W;
    const float4* vec;
    float*        out;
    const float*  bias;
    int r;
    if (row < 3072) { W = w_ih; vec = sx; out = g_gi; bias = b_ih; r = row; }
    else            { W = w_hh; vec = sh; out = g_gh; bias = b_hh; r = row - 3072; }
    const float4* w0 = (const float4*)(W + (long)r * H);
    const float4* w1 = (const float4*)(W + (long)(r + 1) * H);
    float a0 = 0.f, a1 = 0.f;
#pragma unroll
    for (int i = 0; i < 8; i++) {
        float4 b = vec[lane + i * 32];
        a0 += dot4(__ldcs(&w0[lane + i * 32]), b);
        a1 += dot4(__ldcs(&w1[lane + i * 32]), b);
    }
    a0 = wsum(a0); a1 = wsum(a1);
    if (lane == 0) { out[r] = a0 + bias[r]; out[r + 1] = a1 + bias[r + 1]; }
}

// ------------------------- K6: GRU combine -------------------------
__global__ void k6_gru(const float* __restrict__ hidden, float* __restrict__ out_h) {
    int j = blockIdx.x * 256 + threadIdx.x;  // grid 4
    float r = 1.f / (1.f + expf(-(g_gi[j] + g_gh[j])));
    float z = 1.f / (1.f + expf(-(g_gi[H + j] + g_gh[H + j])));
    float n = tanhf(g_gi[2 * H + j] + r * g_gh[2 * H + j]);
    float h = (1.f - z) * n + z * hidden[j];
    g_hnew[j] = h;
    out_h[j]  = h;
}

// ------------------------- K7: vocab logits + running max, 2 rows/warp -------------------------
// grid 8000: 8 warps x 2 rows = 16 rows/block
__global__ void k7_logits(const float* __restrict__ out_w, const float* __restrict__ out_b) {
    __shared__ float4 sh[256];
    __shared__ float red[16];
    int t = threadIdx.x;
    sh[t] = ((const float4*)g_hnew)[t];
    __syncthreads();
    int warp = t >> 5, lane = t & 31;
    int row = blockIdx.x * 16 + warp * 2;
    const float4* w0 = (const float4*)(out_w + (long)row * H);
    const float4* w1 = (const float4*)(out_w + (long)(row + 1) * H);
    float a0 = 0.f, a1 = 0.f;
#pragma unroll
    for (int i = 0; i < 8; i++) {
        float4 b = sh[lane + i * 32];
        a0 += dot4(__ldcs(&w0[lane + i * 32]), b);
        a1 += dot4(__ldcs(&w1[lane + i * 32]), b);
    }
    a0 = wsum(a0); a1 = wsum(a1);
    float l0 = a0 + out_b[row];
    float l1 = a1 + out_b[row + 1];
    if (lane == 0) {
        g_blog[row]     = l0;
        g_blog[row + 1] = l1;
        red[warp * 2]     = l0;
        red[warp * 2 + 1] = l1;
    }
    __syncthreads();
    if (t == 0) {
        float m = red[0];
#pragma unroll
        for (int i = 1; i < 16; i++) m = fmaxf(m, red[i]);
        atomicMax(&g_maxbits, fflip(m));  // max commutative -> deterministic
    }
}

// ------------------------- K8: sum-exp partials (fixed slots -> deterministic) -------------------------
__global__ void k8_psum() {
    __shared__ float red[8];
    int t = threadIdx.x;
    float M = funflip(g_maxbits);
    int base = blockIdx.x * 250;  // 512 * 250 = 128000
    float acc = (t < 250) ? expf(g_blog[base + t] - M) : 0.f;
    acc = wsum(acc);
    if ((t & 31) == 0) red[t >> 5] = acc;
    __syncthreads();
    if (t == 0) {
        float s = 0.f;
#pragma unroll
        for (int i = 0; i < 8; i++) s += red[i];
        g_psum[blockIdx.x] = s;
    }
}

// ------------------------- K9: final log-sum-exp -------------------------
__global__ void k9_lse() {
    __shared__ float red[16];
    int t = threadIdx.x;  // 512
    float v = g_psum[t];
    v = wsum(v);
    if ((t & 31) == 0) red[t >> 5] = v;
    __syncthreads();
    if (t == 0) {
        float s = 0.f;
#pragma unroll
        for (int i = 0; i < 16; i++) s += red[i];
        g_lse = funflip(g_maxbits) + logf(s);
    }
}

// ------------------------- K10: write log-softmax -------------------------
__global__ void k10_out(float* __restrict__ out) {
    int v = blockIdx.x * 256 + threadIdx.x;  // grid 500
    out[v] = g_blog[v] - g_lse;
}

// ------------------------- launch -------------------------
extern "C" void kernel_launch(void* const* d_in, const int* in_sizes, int n_in,
                              void* d_out, int out_size) {
    const int*   ids    = (const int*)d_in[0];
    const float* hidden = (const float*)d_in[1];
    const float* enc    = (const float*)d_in[2];
    const float* emb    = (const float*)d_in[3];
    const float* attn_w = (const float*)d_in[4];
    const float* attn_b = (const float*)d_in[5];
    const float* comb_w = (const float*)d_in[6];
    const float* comb_b = (const float*)d_in[7];
    const float* w_ih   = (const float*)d_in[8];
    const float* w_hh   = (const float*)d_in[9];
    const float* b_ih   = (const float*)d_in[10];
    const float* b_hh   = (const float*)d_in[11];
    const float* out_w  = (const float*)d_in[12];
    const float* out_b  = (const float*)d_in[13];
    float* out = (float*)d_out;

    k1_attn<<<512, 256>>>(ids, hidden, emb, attn_w, attn_b);
    k2_softmax<<<1, 1024>>>(out + V + H);
    k3_ctx<<<256, 256>>>(enc);
    k4a_cat2<<<9, 256>>>(ids, emb);
    k4b_x<<<128, 256>>>(comb_w, comb_b);
    k5_gates<<<384, 256>>>(w_ih, w_hh, b_ih, b_hh, hidden);
    k6_gru<<<4, 256>>>(hidden, out + V);
    k7_logits<<<8000, 256>>>(out_w, out_b);
    k8_psum<<<512, 256>>>();
    k9_lse<<<1, 512>>>();
    k10_out<<<500, 256>>>(out);
}